// round 16
// baseline (speedup 1.0000x reference)
#include <cuda_runtime.h>
#include <cuda_bf16.h>

// L1 TV 1D prox (Condat 2013), batched. y (8,3,256,512) fp32, lmbd (1,3).
// lam = softplus(lmbd[c]). 6144 rows of W=512.
//
// Round 16: TWO ROWS PER THREAD (ILP). Each thread interleaves two
// independent R12-style branchless state machines in one straight-line trip
// body; the two LDS-dependent chains hide each other's latency.
//  - 96 blocks x 32 threads, 64 rows/block (thread t owns rows t and t+32).
//  - phase-split (R12): slim bulk web (no boundary/done), full tail web.
//  - deferred segment emits + forward-fill reconstruction.

#define TV_W 512
#define TV_STRIDE 513            // +1 pad
#define THREADS 32
#define ROWS_PER_BLOCK 64
#define MASK_WORDS 16            // 512 bits per row
#define MASK_STRIDE 17
#define TV_C 3

struct TVState {
    int   k, k0, km, kp;
    float vmin, vmax, umin, umax, fden;
};

// ---- phase 1 trip: k < W-1 only; frozen lanes no-op via 'act' ----
__device__ __forceinline__ void trip1(TVState& s, float* __restrict__ yr,
                                      unsigned* __restrict__ mw,
                                      float lam, float nlam, float lam2)
{
    float yn  = yr[s.k  + 1];
    float rkm = yr[s.km + 1];
    float rkp = yr[s.kp + 1];
    unsigned mold = mw[s.k0 >> 5];

    float fden1 = s.fden + 1.0f;
    float rcp1  = __fdividef(1.0f, fden1);
    float umin_t = s.umin + yn - s.vmin;
    float umax_t = s.umax + yn - s.vmax;

    bool act = s.k < TV_W - 1;
    bool neg = act && (umin_t < nlam);
    bool pos = act && !neg && (umax_t > lam);
    bool jmp = neg || pos;
    bool ext = act && !jmp;

    int   emit_end = neg ? s.km : s.kp;
    int   k0n      = emit_end + 1;
    float rr       = neg ? rkm : rkp;
    float val      = neg ? s.vmin : s.vmax;

    yr[s.k0] = val;
    mw[s.k0 >> 5] = mold | (jmp ? (1u << (s.k0 & 31)) : 0u);

    int  k1 = s.k + 1;
    bool hm = ext && (umin_t >= lam);
    bool hx = ext && (umax_t <= nlam);
    float vmin_ext = hm ? s.vmin + (umin_t - lam) * rcp1 : s.vmin;
    float umin_ext = hm ? lam  : umin_t;
    float vmax_ext = hx ? s.vmax + (umax_t + lam) * rcp1 : s.vmax;
    float umax_ext = hx ? nlam : umax_t;

    s.k    = ext ? k1 : (jmp ? k0n : s.k);
    s.km   = ext ? (hm ? k1 : s.km) : (jmp ? k0n : s.km);
    s.kp   = ext ? (hx ? k1 : s.kp) : (jmp ? k0n : s.kp);
    s.vmin = ext ? vmin_ext : (jmp ? (neg ? rr : rr - lam2) : s.vmin);
    s.vmax = ext ? vmax_ext : (jmp ? (neg ? rr + lam2 : rr) : s.vmax);
    s.umin = ext ? umin_ext : (jmp ? lam  : s.umin);
    s.umax = ext ? umax_ext : (jmp ? nlam : s.umax);
    s.k0   = jmp ? k0n : s.k0;
    s.fden = ext ? fden1 : (jmp ? 1.0f : s.fden);
}

// ---- phase 2 trip: full web incl. boundary + terminate ----
__device__ __forceinline__ void trip2(TVState& s, bool& done,
                                      float* __restrict__ yr,
                                      unsigned* __restrict__ mw,
                                      float lam, float nlam, float lam2)
{
    float yn  = yr[min(s.k  + 1, TV_W - 1)];
    float rkm = yr[min(s.km + 1, TV_W - 1)];
    float rkp = yr[min(s.kp + 1, TV_W - 1)];
    int      wk0  = min(s.k0, TV_W - 1);
    unsigned mold = mw[wk0 >> 5];

    float fden1 = s.fden + 1.0f;
    float rcp1  = __fdividef(1.0f, fden1);
    float umin_t = s.umin + yn - s.vmin;
    float umax_t = s.umax + yn - s.vmax;

    bool alive = !done;
    bool e    = (s.k >= TV_W - 1);
    bool neg  = (e ? (s.umin < 0.0f) : (umin_t < nlam)) && alive;
    bool posr =  e ? (s.umax > 0.0f) : (umax_t > lam);
    bool pos  = !neg && posr && alive;
    bool term = e && !neg && !pos && alive;
    bool ext  = !e && !neg && !pos && alive;
    bool jmp  = neg || pos;

    int   emit_end = neg ? s.km : s.kp;
    int   k0n      = jmp ? emit_end + 1 : s.k0;
    float rr       = neg ? rkm : rkp;
    float val      = neg ? s.vmin : s.vmax;

    yr[wk0] = val;
    mw[wk0 >> 5] = mold | (jmp ? (1u << (wk0 & 31)) : 0u);

    int  k1 = s.k + 1;
    bool hm = ext && (umin_t >= lam);
    bool hx = ext && (umax_t <= nlam);
    float vmin_ext = hm ? s.vmin + (umin_t - lam) * rcp1 : s.vmin;
    float umin_ext = hm ? lam  : umin_t;
    float vmax_ext = hx ? s.vmax + (umax_t + lam) * rcp1 : s.vmax;
    float umax_ext = hx ? nlam : umax_t;

    float vmin_o = s.vmin, vmax_o = s.vmax;
    bool pe = pos && e, pb = pos && !e;
    bool ne = neg && e, nb = neg && !e;

    int   k_n    = ext ? k1 : (jmp ? k0n : s.k);
    int   km_n   = ext ? (hm ? k1 : s.km) : ((neg || pb) ? k0n : s.km);
    int   kp_n   = ext ? (hx ? k1 : s.kp) : ((pos || nb) ? k0n : s.kp);
    float vmin_n = ext ? vmin_ext : (neg ? rr : (pb ? rr - lam2 : vmin_o));
    float vmax_n = ext ? vmax_ext : (pos ? rr : (nb ? rr + lam2 : vmax_o));
    float umin_n = ext ? umin_ext : (pe ? rr - lam - vmin_o : (jmp ? lam  : s.umin));
    float umax_n = ext ? umax_ext : (ne ? rr + lam - vmax_o : (jmp ? nlam : s.umax));
    int   k0_n   = jmp ? k0n : s.k0;
    float fden_n = ext ? fden1 : (jmp ? 1.0f : s.fden);

    s.k = k_n; s.km = km_n; s.kp = kp_n; s.k0 = k0_n;
    s.vmin = vmin_n; s.vmax = vmax_n; s.umin = umin_n; s.umax = umax_n;
    s.fden = fden_n;
    done = done || term;
}

__device__ __forceinline__ void tv_init(TVState& s, const float* yr, float lam)
{
    s.k = 0; s.k0 = 0; s.km = 0; s.kp = 0;
    float y0 = yr[0];
    s.vmin = y0 - lam; s.vmax = y0 + lam;
    s.umin = lam;      s.umax = -lam;
    s.fden = 1.0f;
}

__global__ void __launch_bounds__(THREADS, 1)
tv1d_condat_kernel(const float* __restrict__ y,
                   const float* __restrict__ lmbd,
                   float* __restrict__ out)
{
    extern __shared__ float s[];
    float* rows = s;                                          // 64 * 513
    unsigned* maskbuf = (unsigned*)(s + ROWS_PER_BLOCK * TV_STRIDE);

    const int tid = threadIdx.x;
    const size_t base = (size_t)blockIdx.x * ROWS_PER_BLOCK * TV_W;

    // ---- coalesced staged load (float4) ----
    {
        const float4* g4 = (const float4*)(y + base);
        #pragma unroll 4
        for (int i = tid; i < ROWS_PER_BLOCK * (TV_W / 4); i += THREADS) {
            int r = i >> 7;            // / 128
            int q = i & 127;           // % 128
            float4 v = g4[i];
            float* d = rows + r * TV_STRIDE + (q << 2);
            d[0] = v.x; d[1] = v.y; d[2] = v.z; d[3] = v.w;
        }
    }
    #pragma unroll
    for (int i = tid; i < ROWS_PER_BLOCK * MASK_STRIDE; i += THREADS)
        maskbuf[i] = 0u;
    __syncwarp();

    // ---- dual state machines per thread ----
    float*    yrA = rows    + tid        * TV_STRIDE;
    float*    yrB = rows    + (tid + 32) * TV_STRIDE;
    unsigned* mwA = maskbuf + tid        * MASK_STRIDE;
    unsigned* mwB = maskbuf + (tid + 32) * MASK_STRIDE;
    {
        const int rowA = blockIdx.x * ROWS_PER_BLOCK + tid;
        const int rowB = rowA + 32;
        const float lamA  = log1pf(expf(lmbd[(rowA >> 8) % TV_C]));
        const float lamB  = log1pf(expf(lmbd[(rowB >> 8) % TV_C]));
        const float nlamA = -lamA, nlamB = -lamB;
        const float lam2A = 2.0f * lamA, lam2B = 2.0f * lamB;

        TVState a, b;
        tv_init(a, yrA, lamA);
        tv_init(b, yrB, lamB);

        // ======== PHASE 1 ========
        #pragma unroll 1
        for (int it = 0; it < 2048; ++it) {
            if (!__any_sync(0xFFFFFFFFu, (a.k < TV_W - 1) | (b.k < TV_W - 1)))
                break;
            #pragma unroll
            for (int u = 0; u < 4; ++u) {
                trip1(a, yrA, mwA, lamA, nlamA, lam2A);
                trip1(b, yrB, mwB, lamB, nlamB, lam2B);
            }
        }

        // ======== PHASE 2 (short tail) ========
        bool doneA = false, doneB = false;
        #pragma unroll 1
        for (int it = 0; it < 4096; ++it) {
            if (!__any_sync(0xFFFFFFFFu, (!doneA) | (!doneB))) break;
            trip2(a, doneA, yrA, mwA, lamA, nlamA, lam2A);
            trip2(b, doneB, yrB, mwB, lamB, nlamB, lam2B);
        }

        // --- final (terminate) segment marks ---
        {
            int wk0 = min(a.k0, TV_W - 1);
            yrA[wk0] = a.vmin + a.umin / a.fden;
            mwA[wk0 >> 5] |= 1u << (wk0 & 31);
        }
        {
            int wk0 = min(b.k0, TV_W - 1);
            yrB[wk0] = b.vmin + b.umin / b.fden;
            mwB[wk0 >> 5] |= 1u << (wk0 & 31);
        }

        // --- forward-fill both rows ---
        #pragma unroll 1
        for (int half = 0; half < 2; ++half) {
            float*    yr = half ? yrB : yrA;
            unsigned* mw = half ? mwB : mwA;
            float v = 0.0f;
            #pragma unroll 1
            for (int w = 0; w < MASK_WORDS; ++w) {
                unsigned m = mw[w];
                float* p = yr + (w << 5);
                #pragma unroll
                for (int bb = 0; bb < 32; ++bb) {
                    float x = p[bb];
                    v = ((m >> bb) & 1u) ? x : v;
                    p[bb] = v;
                }
            }
        }
    }
    __syncwarp();

    // ---- coalesced staged store (float4) ----
    {
        float4* o4 = (float4*)(out + base);
        #pragma unroll 4
        for (int i = tid; i < ROWS_PER_BLOCK * (TV_W / 4); i += THREADS) {
            int r = i >> 7;
            int q = i & 127;
            const float* d = rows + r * TV_STRIDE + (q << 2);
            o4[i] = make_float4(d[0], d[1], d[2], d[3]);
        }
    }
}

extern "C" void kernel_launch(void* const* d_in, const int* in_sizes, int n_in,
                              void* d_out, int out_size)
{
    const float* y    = (const float*)d_in[0];
    const float* lmbd = (const float*)d_in[1];
    float* out        = (float*)d_out;

    const int n_rows = in_sizes[0] / TV_W;            // 6144
    const int blocks = n_rows / ROWS_PER_BLOCK;       // 96
    const int smem   = (ROWS_PER_BLOCK * TV_STRIDE) * sizeof(float)
                     + (ROWS_PER_BLOCK * MASK_STRIDE) * sizeof(unsigned); // 135680 B

    cudaFuncSetAttribute(tv1d_condat_kernel,
                         cudaFuncAttributeMaxDynamicSharedMemorySize, smem);

    tv1d_condat_kernel<<<blocks, THREADS, smem>>>(y, lmbd, out);
    (void)n_in; (void)out_size;
}

// round 17
// speedup vs baseline: 1.9516x; 1.9516x over previous
#include <cuda_runtime.h>
#include <cuda_bf16.h>

// L1 TV 1D prox (Condat 2013), batched. y (8,3,256,512) fp32, lmbd (1,3).
// lam = softplus(lmbd[c]). 6144 rows of W=512, ONE THREAD PER ROW.
//
// Round 17 = R12 phase-split winner + both per-trip memory recurrences removed:
//  - software-pipelined loads: next trip's yn/rkm/rkp selected from values
//    prefetched THIS trip (yr[k+2], yr[km+2], yr[kp+2]) -> LDS off the chain.
//  - byte-flag segment marks: unconditional mb[k0] = jmp store (no RMW).
//    Safe: k0 strictly increases past set flags.
//  - deferred segment emits + forward-fill reconstruction (proven R8-R12).

#define TV_W 512
#define TV_STRIDE 513            // +1 pad
#define THREADS 32
#define MB_STRIDE 516            // byte-flag row stride (4-aligned)
#define TV_C 3

__global__ void __launch_bounds__(THREADS, 1)
tv1d_condat_kernel(const float* __restrict__ y,
                   const float* __restrict__ lmbd,
                   float* __restrict__ out)
{
    extern __shared__ float s[];
    float* rows = s;                                   // 32 * 513 floats
    unsigned char* mbase = (unsigned char*)(s + THREADS * TV_STRIDE);

    const int tid = threadIdx.x;
    const size_t base = (size_t)blockIdx.x * THREADS * TV_W;

    // ---- coalesced staged load (float4) ----
    {
        const float4* g4 = (const float4*)(y + base);
        #pragma unroll 4
        for (int i = tid; i < THREADS * (TV_W / 4); i += THREADS) {
            int r = i >> 7;            // / 128
            int q = i & 127;           // % 128
            float4 v = g4[i];
            float* d = rows + r * TV_STRIDE + (q << 2);
            d[0] = v.x; d[1] = v.y; d[2] = v.z; d[3] = v.w;
        }
    }
    unsigned char* mb = mbase + tid * MB_STRIDE;
    {   // zero flags (uint stores, rows are 4-aligned: MB_STRIDE % 4 == 0)
        unsigned* mbw = (unsigned*)mb;
        #pragma unroll
        for (int w = 0; w < TV_W / 4; ++w) mbw[w] = 0u;
    }
    __syncwarp();

    // ---- branchless Condat state machine ----
    float* yr = rows + tid * TV_STRIDE;
    {
        const int row = blockIdx.x * THREADS + tid;
        const int c   = (row >> 8) % TV_C;            // (row/256)%3
        const float lam  = log1pf(expf(lmbd[c]));     // softplus
        const float nlam = -lam;
        const float lam2 = 2.0f * lam;

        int   k = 0, k0 = 0, km = 0, kp = 0;
        float y0   = yr[0];
        float vmin = y0 - lam;
        float vmax = y0 + lam;
        float umin = lam;
        float umax = nlam;
        float fden = 1.0f;        // invariant: fden == (k - k0 + 1)

        // carried loads: yn = yr[k+1], rkm = yr[km+1], rkp = yr[kp+1]
        float yn  = yr[1];
        float rkm = yn;
        float rkp = yn;

        // ======== PHASE 1: k < W-1 only (pipelined, no boundary logic) ====
        #pragma unroll 1
        for (int it = 0; it < 512; ++it) {
            if (!__any_sync(0xFFFFFFFFu, k < TV_W - 1)) break;
            #pragma unroll
            for (int u = 0; u < 8; ++u) {
                // prefetch for NEXT trip (results consumed ~40 instr later).
                // max index 513: lands in pad/flag region of smem, harmless
                // (only reachable for frozen lanes whose state won't change).
                float q_k = yr[k  + 2];
                float q_m = yr[km + 2];
                float q_p = yr[kp + 2];

                float fden1 = fden + 1.0f;
                float rcp1  = __fdividef(1.0f, fden1);
                float umin_t = umin + yn - vmin;
                float umax_t = umax + yn - vmax;

                bool act = k < TV_W - 1;
                bool neg = act && (umin_t < nlam);
                bool pos = act && !neg && (umax_t > lam);
                bool jmp = neg || pos;
                bool ext = act && !jmp;

                int   emit_end = neg ? km : kp;
                int   k0n      = emit_end + 1;
                float rr       = neg ? rkm : rkp;   // == yr[k0n] on jump
                float val      = neg ? vmin : vmax;

                // deferred emit: value + byte flag, both unconditional.
                yr[k0] = val;
                mb[k0] = (unsigned char)jmp;

                int  k1 = k + 1;
                bool hm = ext && (umin_t >= lam);
                bool hx = ext && (umax_t <= nlam);
                float vmin_ext = hm ? vmin + (umin_t - lam) * rcp1 : vmin;
                float umin_ext = hm ? lam  : umin_t;
                float vmax_ext = hx ? vmax + (umax_t + lam) * rcp1 : vmax;
                float umax_ext = hx ? nlam : umax_t;

                k    = ext ? k1 : (jmp ? k0n : k);
                km   = ext ? (hm ? k1 : km) : (jmp ? k0n : km);
                kp   = ext ? (hx ? k1 : kp) : (jmp ? k0n : kp);
                vmin = ext ? vmin_ext : (jmp ? (neg ? rr : rr - lam2) : vmin);
                vmax = ext ? vmax_ext : (jmp ? (neg ? rr + lam2 : rr) : vmax);
                umin = ext ? umin_ext : (jmp ? lam  : umin);
                umax = ext ? umax_ext : (jmp ? nlam : umax);
                k0   = jmp ? k0n : k0;
                fden = ext ? fden1 : (jmp ? 1.0f : fden);

                // forward carried loads for next trip
                float q_j = neg ? q_m : q_p;        // yr[k0n+1] on jump
                yn  = ext ? q_k : (jmp ? q_j : yn);
                rkm = ext ? (hm ? q_k : rkm) : (jmp ? q_j : rkm);
                rkp = ext ? (hx ? q_k : rkp) : (jmp ? q_j : rkp);
            }
        }

        // ======== PHASE 2: full web (boundary + terminate), short tail ====
        bool done = false;
        #pragma unroll 1
        for (int it = 0; it < 4096; ++it) {
            if (!__any_sync(0xFFFFFFFFu, !done)) break;

            float yn2  = yr[min(k  + 1, TV_W - 1)];
            float rkm2 = yr[min(km + 1, TV_W - 1)];
            float rkp2 = yr[min(kp + 1, TV_W - 1)];
            int   wk0  = min(k0, TV_W - 1);

            float fden1 = fden + 1.0f;
            float rcp1  = __fdividef(1.0f, fden1);
            float umin_t = umin + yn2 - vmin;
            float umax_t = umax + yn2 - vmax;

            bool alive = !done;
            bool e    = (k >= TV_W - 1);
            bool neg  = (e ? (umin < 0.0f) : (umin_t < nlam)) && alive;
            bool posr =  e ? (umax > 0.0f) : (umax_t > lam);
            bool pos  = !neg && posr && alive;
            bool term = e && !neg && !pos && alive;
            bool ext  = !e && !neg && !pos && alive;
            bool jmp  = neg || pos;

            int   emit_end = neg ? km : kp;
            int   k0n      = jmp ? emit_end + 1 : k0;
            float rr       = neg ? rkm2 : rkp2;
            float val      = neg ? vmin : vmax;

            yr[wk0] = val;
            mb[wk0] = (unsigned char)jmp;

            int  k1 = k + 1;
            bool hm = ext && (umin_t >= lam);
            bool hx = ext && (umax_t <= nlam);
            float vmin_ext = hm ? vmin + (umin_t - lam) * rcp1 : vmin;
            float umin_ext = hm ? lam  : umin_t;
            float vmax_ext = hx ? vmax + (umax_t + lam) * rcp1 : vmax;
            float umax_ext = hx ? nlam : umax_t;

            float vmin_o = vmin, vmax_o = vmax;
            bool pe = pos && e, pb = pos && !e;
            bool ne = neg && e, nb = neg && !e;

            int   k_n    = ext ? k1 : (jmp ? k0n : k);
            int   km_n   = ext ? (hm ? k1 : km) : ((neg || pb) ? k0n : km);
            int   kp_n   = ext ? (hx ? k1 : kp) : ((pos || nb) ? k0n : kp);
            float vmin_n = ext ? vmin_ext : (neg ? rr : (pb ? rr - lam2 : vmin_o));
            float vmax_n = ext ? vmax_ext : (pos ? rr : (nb ? rr + lam2 : vmax_o));
            float umin_n = ext ? umin_ext : (pe ? rr - lam - vmin_o : (jmp ? lam  : umin));
            float umax_n = ext ? umax_ext : (ne ? rr + lam - vmax_o : (jmp ? nlam : umax));
            int   k0_n   = jmp ? k0n : k0;
            float fden_n = ext ? fden1 : (jmp ? 1.0f : fden);

            k = k_n; km = km_n; kp = kp_n; k0 = k0_n;
            vmin = vmin_n; vmax = vmax_n; umin = umin_n; umax = umax_n;
            fden = fden_n;
            done = done || term;
        }

        // --- final (terminate) segment mark ---
        {
            int wk0 = min(k0, TV_W - 1);
            yr[wk0] = vmin + umin / fden;
            mb[wk0] = 1;
        }

        // --- forward-fill: expand (start,value) marks to full row ---
        {
            const unsigned* mbw = (const unsigned*)mb;
            float v = 0.0f;
            #pragma unroll 1
            for (int w = 0; w < TV_W / 4; ++w) {
                unsigned f4 = mbw[w];          // 4 flags, one per byte
                float* p = yr + (w << 2);
                #pragma unroll
                for (int b = 0; b < 4; ++b) {
                    float x = p[b];
                    v = ((f4 >> (b * 8)) & 0xFFu) ? x : v;
                    p[b] = v;
                }
            }
        }
    }
    __syncwarp();

    // ---- coalesced staged store (float4) ----
    {
        float4* o4 = (float4*)(out + base);
        #pragma unroll 4
        for (int i = tid; i < THREADS * (TV_W / 4); i += THREADS) {
            int r = i >> 7;
            int q = i & 127;
            const float* d = rows + r * TV_STRIDE + (q << 2);
            o4[i] = make_float4(d[0], d[1], d[2], d[3]);
        }
    }
}

extern "C" void kernel_launch(void* const* d_in, const int* in_sizes, int n_in,
                              void* d_out, int out_size)
{
    const float* y    = (const float*)d_in[0];
    const float* lmbd = (const float*)d_in[1];
    float* out        = (float*)d_out;

    const int n_rows = in_sizes[0] / TV_W;       // 6144
    const int blocks = n_rows / THREADS;         // 192
    const int smem   = (THREADS * TV_STRIDE) * sizeof(float)
                     + THREADS * MB_STRIDE;      // 65664 + 16512 = 82176 B

    cudaFuncSetAttribute(tv1d_condat_kernel,
                         cudaFuncAttributeMaxDynamicSharedMemorySize, smem);

    tv1d_condat_kernel<<<blocks, THREADS, smem>>>(y, lmbd, out);
    (void)n_in; (void)out_size;
}